// round 2
// baseline (speedup 1.0000x reference)
#include <cuda_runtime.h>
#include <cuda_bf16.h>
#include <cstdint>

#define KN 8192
#define KD 8
#define TI 256   // i-rows per block (one per thread)
#define TJ 512   // j-rows per shared tile

// Scratch (device globals: no allocation allowed in kernel_launch)
__device__ int g_counts[2 * KN];   // dominance counts per row, per matrix
__device__ int g_hist[2 * KN];     // histogram of counts per matrix

// ---------------------------------------------------------------------------
// 0) zero scratch (must run every launch: graph replays must be deterministic)
// ---------------------------------------------------------------------------
__global__ void kdm_zero_kernel() {
    int idx = blockIdx.x * blockDim.x + threadIdx.x;
    if (idx < 2 * KN) { g_counts[idx] = 0; g_hist[idx] = 0; }
}

// ---------------------------------------------------------------------------
// 1) dominance counting: for each i, count j with X[i,d] > X[j,d] for all d
//    grid = (KN/TI, KN/TJ, 2); block = TI threads.
//    Each thread owns one i (8 floats in registers). The j-loop index is
//    uniform across the warp -> LDS reads are broadcast (conflict-free).
// ---------------------------------------------------------------------------
__global__ __launch_bounds__(TI) void kdm_dom_kernel(
    const float* __restrict__ X, const float* __restrict__ Xh)
{
    const int mat = blockIdx.z;
    const float* __restrict__ src = mat ? Xh : X;

    __shared__ float4 sj[TJ * 2];   // TJ rows x 8 floats = 16 KB

    const int j0 = blockIdx.y * TJ;
    // cooperative coalesced tile load
    const float4* gj = reinterpret_cast<const float4*>(src + (size_t)j0 * KD);
    #pragma unroll
    for (int k = threadIdx.x; k < TJ * 2; k += TI)
        sj[k] = gj[k];
    __syncthreads();

    const int i = blockIdx.x * TI + threadIdx.x;
    const float4 a0 = reinterpret_cast<const float4*>(src + (size_t)i * KD)[0];
    const float4 a1 = reinterpret_cast<const float4*>(src + (size_t)i * KD)[1];

    int cnt = 0;
    #pragma unroll 4
    for (int j = 0; j < TJ; j++) {
        const float4 b0 = sj[2 * j];
        const float4 b1 = sj[2 * j + 1];
        float m;
        m =          a0.x - b0.x;
        m = fminf(m, a0.y - b0.y);
        m = fminf(m, a0.z - b0.z);
        m = fminf(m, a0.w - b0.w);
        m = fminf(m, a1.x - b1.x);
        m = fminf(m, a1.y - b1.y);
        m = fminf(m, a1.z - b1.z);
        m = fminf(m, a1.w - b1.w);
        cnt += (m > 0.0f);          // i==j gives m==0 -> excluded, as required
    }
    atomicAdd(&g_counts[mat * KN + i], cnt);
}

// ---------------------------------------------------------------------------
// 2) histogram the integer counts (values are in [0, KN-1])
// ---------------------------------------------------------------------------
__global__ void kdm_hist_kernel() {
    int idx = blockIdx.x * blockDim.x + threadIdx.x;
    if (idx < 2 * KN) {
        int mat = idx >= KN;
        int v = g_counts[idx];
        atomicAdd(&g_hist[mat * KN + v], 1);
    }
}

// ---------------------------------------------------------------------------
// 3) finalize: sum_r |sortA_r - sortB_r| == sum_t |cumA(t) - cumB(t)|  (W1
//    identity for equal-size integer samples). Single block, 1024 threads,
//    8 bins/thread, Hillis-Steele scan of per-thread totals.
//    result = S / ((N-1) * N)
// ---------------------------------------------------------------------------
__global__ __launch_bounds__(1024) void kdm_finalize_kernel(float* __restrict__ out) {
    __shared__ int s[1024];
    const int tid = threadIdx.x;
    const int base = tid * 8;

    int d[8];
    int tot = 0;
    #pragma unroll
    for (int k = 0; k < 8; k++) {
        d[k] = g_hist[base + k] - g_hist[KN + base + k];
        tot += d[k];
    }
    s[tid] = tot;
    __syncthreads();

    // inclusive scan over the 1024 per-thread totals
    #pragma unroll
    for (int off = 1; off < 1024; off <<= 1) {
        int v = (tid >= off) ? s[tid - off] : 0;
        __syncthreads();
        s[tid] += v;
        __syncthreads();
    }
    const int excl = s[tid] - tot;

    int run = excl;
    int acc = 0;
    #pragma unroll
    for (int k = 0; k < 8; k++) {
        run += d[k];
        acc += (run >= 0) ? run : -run;   // |cum(t)|; last bin's cum is 0 anyway
    }

    __syncthreads();
    s[tid] = acc;
    __syncthreads();
    #pragma unroll
    for (int off = 512; off > 0; off >>= 1) {
        if (tid < off) s[tid] += s[tid + off];
        __syncthreads();
    }
    if (tid == 0)
        out[0] = (float)s[0] / ((float)KN * (float)(KN - 1));
}

// ---------------------------------------------------------------------------
extern "C" void kernel_launch(void* const* d_in, const int* in_sizes, int n_in,
                              void* d_out, int out_size) {
    const float* X  = (const float*)d_in[0];
    const float* Xh = (const float*)d_in[1];
    float* out = (float*)d_out;

    kdm_zero_kernel<<<(2 * KN + 1023) / 1024, 1024>>>();
    dim3 grid(KN / TI, KN / TJ, 2);
    kdm_dom_kernel<<<grid, TI>>>(X, Xh);
    kdm_hist_kernel<<<(2 * KN + 255) / 256, 256>>>();
    kdm_finalize_kernel<<<1, 1024>>>(out);
}

// round 3
// speedup vs baseline: 1.2675x; 1.2675x over previous
#include <cuda_runtime.h>
#include <cuda_bf16.h>
#include <cstdint>

#define KN   8192
#define KD   8
#define NTHR 256
#define IPT  2
#define ITILE (NTHR * IPT)   // 512 i-rows per block
#define TJ   256             // j-rows per shared tile

// Scratch. Statics start zeroed; each kernel re-zeroes what it consumed, so
// every graph replay sees the same initial state (deterministic).
__device__ int g_counts[2 * KN];   // per-i count of NON-dominated j (incl. self-as-dominated quirk)
__device__ int g_hist[2 * KN];     // histogram of dominance counts per matrix

// packed fp32x2 add (sm_100+); returns the two 32-bit halves (reg-pair split is free)
__device__ __forceinline__ void addx2(unsigned &lo, unsigned &hi,
                                      unsigned long long a, unsigned long long b) {
    unsigned long long d;
    asm("add.rn.f32x2 %0, %1, %2;" : "=l"(d) : "l"(a), "l"(b));
    lo = (unsigned)d;
    hi = (unsigned)(d >> 32);
}

// ---------------------------------------------------------------------------
// 1) dominance: thread owns 2 i-rows (registers); j-tile negated in smem.
//    Per j: 2 LDS.128 + per-i {4 FADD2 + 4 LOP3 + SHF + IADD}.
//    neg[i] += (any diff sign-set). Diagonal contributes 0 -> count = 8191-neg.
// ---------------------------------------------------------------------------
__global__ __launch_bounds__(NTHR) void kdm_dom(const float* __restrict__ X,
                                                const float* __restrict__ Xh) {
    const int mat = blockIdx.z;
    const float* __restrict__ src = mat ? Xh : X;

    __shared__ unsigned long long sj[TJ * 4];   // 256 rows x 8 floats (negated) = 8 KB

    // cooperative negated tile fill
    const float* gj = src + (size_t)blockIdx.y * TJ * KD;
    #pragma unroll
    for (int k = threadIdx.x; k < TJ * KD / 4; k += NTHR) {
        float4 v = reinterpret_cast<const float4*>(gj)[k];
        reinterpret_cast<float4*>(sj)[k] = make_float4(-v.x, -v.y, -v.z, -v.w);
    }

    const int ibase = blockIdx.x * ITILE + threadIdx.x;
    unsigned long long a[IPT][4];
    #pragma unroll
    for (int p = 0; p < IPT; p++) {
        const unsigned long long* ar =
            reinterpret_cast<const unsigned long long*>(src + (size_t)(ibase + p * NTHR) * KD);
        a[p][0] = ar[0]; a[p][1] = ar[1]; a[p][2] = ar[2]; a[p][3] = ar[3];
    }
    __syncthreads();

    unsigned neg[IPT] = {0, 0};
    #pragma unroll 4
    for (int j = 0; j < TJ; j++) {
        const unsigned long long b0 = sj[j * 4 + 0];
        const unsigned long long b1 = sj[j * 4 + 1];
        const unsigned long long b2 = sj[j * 4 + 2];
        const unsigned long long b3 = sj[j * 4 + 3];
        #pragma unroll
        for (int p = 0; p < IPT; p++) {
            unsigned x0, x1, x2, x3, x4, x5, x6, x7;
            addx2(x0, x1, a[p][0], b0);
            addx2(x2, x3, a[p][1], b1);
            addx2(x4, x5, a[p][2], b2);
            addx2(x6, x7, a[p][3], b3);
            const unsigned o = (x0 | x1 | x2) | (x3 | x4 | x5) | (x6 | x7);
            neg[p] += o >> 31;   // 1 if any diff negative -> i does NOT dominate j
        }
    }
    #pragma unroll
    for (int p = 0; p < IPT; p++)
        atomicAdd(&g_counts[mat * KN + ibase + p * NTHR], (int)neg[p]);
}

// ---------------------------------------------------------------------------
// 2) histogram counts (and re-zero g_counts for the next replay)
// ---------------------------------------------------------------------------
__global__ __launch_bounds__(1024) void kdm_hist() {
    const int slot = blockIdx.x * 1024 + threadIdx.x;
    const int neg = g_counts[slot];
    g_counts[slot] = 0;
    const int v = (KN - 1) - neg;           // true dominance count in [0, 8191]
    atomicAdd(&g_hist[(slot >> 13) * KN + v], 1);
}

// ---------------------------------------------------------------------------
// 3) finalize: W1 identity  sum_r|sortA_r - sortB_r| = sum_t|cumA(t)-cumB(t)|
//    shfl-based scan (3 barriers). Also re-zeroes g_hist.
// ---------------------------------------------------------------------------
__global__ __launch_bounds__(1024) void kdm_fin(float* __restrict__ out) {
    __shared__ int wsum[32];
    const int tid = threadIdx.x, lane = tid & 31, wid = tid >> 5;
    const int base = tid * 8;

    int d[8], tot = 0;
    #pragma unroll
    for (int k = 0; k < 8; k++) {
        const int ha = g_hist[base + k];
        const int hb = g_hist[KN + base + k];
        g_hist[base + k] = 0;
        g_hist[KN + base + k] = 0;
        d[k] = ha - hb;
        tot += d[k];
    }

    // inclusive warp scan of per-thread totals
    int v = tot;
    #pragma unroll
    for (int off = 1; off < 32; off <<= 1) {
        const int n = __shfl_up_sync(0xffffffffu, v, off);
        if (lane >= off) v += n;
    }
    if (lane == 31) wsum[wid] = v;
    __syncthreads();
    if (wid == 0) {
        int w = wsum[lane];
        #pragma unroll
        for (int off = 1; off < 32; off <<= 1) {
            const int n = __shfl_up_sync(0xffffffffu, w, off);
            if (lane >= off) w += n;
        }
        wsum[lane] = w;
    }
    __syncthreads();

    const int excl = v - tot + (wid ? wsum[wid - 1] : 0);
    int run = excl, acc = 0;
    #pragma unroll
    for (int k = 0; k < 8; k++) {
        run += d[k];
        acc += (run >= 0) ? run : -run;
    }

    // block reduce acc
    #pragma unroll
    for (int off = 16; off; off >>= 1) acc += __shfl_down_sync(0xffffffffu, acc, off);
    __syncthreads();                  // all reads of wsum above are done
    if (lane == 0) wsum[wid] = acc;
    __syncthreads();
    if (wid == 0) {
        int r = wsum[lane];
        #pragma unroll
        for (int off = 16; off; off >>= 1) r += __shfl_down_sync(0xffffffffu, r, off);
        if (lane == 0) out[0] = (float)r / ((float)KN * (float)(KN - 1));
    }
}

// ---------------------------------------------------------------------------
extern "C" void kernel_launch(void* const* d_in, const int* in_sizes, int n_in,
                              void* d_out, int out_size) {
    const float* X  = (const float*)d_in[0];
    const float* Xh = (const float*)d_in[1];
    float* out = (float*)d_out;

    dim3 grid(KN / ITILE, KN / TJ, 2);          // (16, 32, 2) = 1024 blocks
    kdm_dom<<<grid, NTHR>>>(X, Xh);
    kdm_hist<<<2 * KN / 1024, 1024>>>();
    kdm_fin<<<1, 1024>>>(out);
}

// round 4
// speedup vs baseline: 1.3317x; 1.0507x over previous
#include <cuda_runtime.h>
#include <cuda_bf16.h>
#include <cstdint>

#define KN    8192
#define KD    8
#define NTHR  256
#define IPT   2
#define ITILE 512            // i-rows per dom block
#define TJ    256            // j-rows per shared tile
#define NSEG  8
#define SEGSZ 1024
#define NTILES 272           // sum_{ti=0..15} (2*ti+2)

// Scratch (device globals; statics start zeroed, every consumer re-zeroes or
// fully overwrites -> graph replays are deterministic).
__device__ float    g_rows[2][KN][KD];   // rows sorted ascending by dim 0
__device__ unsigned g_keys[2][KN];       // segment-sorted sortable keys
__device__ int      g_kidx[2][KN];       // original row ids per segment-sorted pos
__device__ int      g_counts[2 * KN];    // per sorted-row "neg" counts

__device__ __forceinline__ unsigned f2sortable(float f) {
    unsigned u = __float_as_uint(f);
    return (u & 0x80000000u) ? ~u : (u | 0x80000000u);
}

// packed fp32x2 add (sm_100+)
__device__ __forceinline__ void addx2(unsigned &lo, unsigned &hi,
                                      unsigned long long a, unsigned long long b) {
    unsigned long long d;
    asm("add.rn.f32x2 %0, %1, %2;" : "=l"(d) : "l"(a), "l"(b));
    lo = (unsigned)d;
    hi = (unsigned)(d >> 32);
}

// ---------------------------------------------------------------------------
// S1) bitonic-sort 1024-row segments by dim-0 key (16 blocks total)
// ---------------------------------------------------------------------------
__global__ __launch_bounds__(SEGSZ) void kdm_sort_seg(const float* __restrict__ X,
                                                      const float* __restrict__ Xh) {
    const int m = blockIdx.y;
    const float* __restrict__ src = m ? Xh : X;
    __shared__ unsigned sk[SEGSZ];
    __shared__ int      si[SEGSZ];
    const int tid = threadIdx.x;
    const int e0  = blockIdx.x * SEGSZ;

    sk[tid] = f2sortable(src[(size_t)(e0 + tid) * KD]);
    si[tid] = e0 + tid;
    __syncthreads();

    for (int k = 2; k <= SEGSZ; k <<= 1) {
        for (int j = k >> 1; j > 0; j >>= 1) {
            const int ixj = tid ^ j;
            if (ixj > tid) {
                const bool up = (tid & k) == 0;
                const unsigned a = sk[tid], b = sk[ixj];
                if ((a > b) == up) {
                    sk[tid] = b; sk[ixj] = a;
                    const int t = si[tid]; si[tid] = si[ixj]; si[ixj] = t;
                }
            }
            __syncthreads();
        }
    }
    g_keys[m][e0 + tid] = sk[tid];
    g_kidx[m][e0 + tid] = si[tid];
}

// ---------------------------------------------------------------------------
// S2) global rank via cross-segment binary search (lb/ub -> exact permutation),
//     then gather full rows into g_rows at their rank.
// ---------------------------------------------------------------------------
__global__ __launch_bounds__(256) void kdm_rank_gather(const float* __restrict__ X,
                                                       const float* __restrict__ Xh) {
    const int m = blockIdx.y;
    const float* __restrict__ src = m ? Xh : X;
    __shared__ unsigned sk[KN];   // 32 KB
    for (int k = threadIdx.x; k < KN; k += 256) sk[k] = g_keys[m][k];
    __syncthreads();

    const int e   = blockIdx.x * 256 + threadIdx.x;
    const int s   = e >> 10;
    const int pos = e & (SEGSZ - 1);
    const unsigned key = sk[e];

    int rank = pos;
    #pragma unroll
    for (int t = 0; t < NSEG; t++) {
        if (t == s) continue;
        const unsigned* seg = sk + t * SEGSZ;
        int lo = 0, hi = SEGSZ;
        if (t < s) { // count <= key
            while (lo < hi) { const int mid = (lo + hi) >> 1; if (seg[mid] <= key) lo = mid + 1; else hi = mid; }
        } else {     // count < key
            while (lo < hi) { const int mid = (lo + hi) >> 1; if (seg[mid] <  key) lo = mid + 1; else hi = mid; }
        }
        rank += lo;
    }

    const int orig = g_kidx[m][e];
    const float4* r = reinterpret_cast<const float4*>(src + (size_t)orig * KD);
    float4* w = reinterpret_cast<float4*>(&g_rows[m][rank][0]);
    w[0] = r[0];
    w[1] = r[1];
}

// ---------------------------------------------------------------------------
// D) triangular dominance on sorted rows. Tile b -> (ti, tj) with
//    tj in [0, 2*ti+2). neg counts (not-dominated OR invalid-j); finalize
//    recovers dominated = 512*(ti+1) - neg.
// ---------------------------------------------------------------------------
__global__ __launch_bounds__(NTHR) void kdm_dom() {
    const int m = blockIdx.y;
    const int b = blockIdx.x;
    int ti = (int)((sqrtf(4.0f * (float)b + 1.0f) - 1.0f) * 0.5f);
    while (ti * (ti + 1) > b) --ti;
    while ((ti + 1) * (ti + 2) <= b) ++ti;
    const int tj = b - ti * (ti + 1);
    const int i0 = ti << 9;
    const int j0 = tj << 8;

    __shared__ unsigned long long sj[TJ * 4];   // 8 KB, negated j-rows

    const float* gj = &g_rows[m][j0][0];
    #pragma unroll
    for (int k = threadIdx.x; k < TJ * KD / 4; k += NTHR) {
        const float4 v = reinterpret_cast<const float4*>(gj)[k];
        reinterpret_cast<float4*>(sj)[k] = make_float4(-v.x, -v.y, -v.z, -v.w);
    }

    const int ib = i0 + threadIdx.x;
    unsigned long long a[IPT][4];
    #pragma unroll
    for (int p = 0; p < IPT; p++) {
        const unsigned long long* ar =
            reinterpret_cast<const unsigned long long*>(&g_rows[m][ib + p * NTHR][0]);
        a[p][0] = ar[0]; a[p][1] = ar[1]; a[p][2] = ar[2]; a[p][3] = ar[3];
    }
    __syncthreads();

    unsigned neg[IPT] = {0, 0};

    if (j0 + TJ <= i0) {
        // interior: all j in tile precede every i of this block
        #pragma unroll 4
        for (int j = 0; j < TJ; j++) {
            const unsigned long long b0 = sj[j * 4 + 0];
            const unsigned long long b1 = sj[j * 4 + 1];
            const unsigned long long b2 = sj[j * 4 + 2];
            const unsigned long long b3 = sj[j * 4 + 3];
            #pragma unroll
            for (int p = 0; p < IPT; p++) {
                unsigned x0, x1, x2, x3, x4, x5, x6, x7;
                addx2(x0, x1, a[p][0], b0);
                addx2(x2, x3, a[p][1], b1);
                addx2(x4, x5, a[p][2], b2);
                addx2(x6, x7, a[p][3], b3);
                const unsigned o = (x0 | x1 | x2) | (x3 | x4 | x5) | (x6 | x7);
                neg[p] += o >> 31;
            }
        }
    } else {
        // diagonal: j valid only when (j0 + j) < i  <=>  j < lim_p
        const int lim0 = ib - j0;
        const int lim1 = ib + NTHR - j0;
        #pragma unroll 4
        for (int j = 0; j < TJ; j++) {
            const unsigned long long b0 = sj[j * 4 + 0];
            const unsigned long long b1 = sj[j * 4 + 1];
            const unsigned long long b2 = sj[j * 4 + 2];
            const unsigned long long b3 = sj[j * 4 + 3];
            {
                unsigned x0, x1, x2, x3, x4, x5, x6, x7;
                addx2(x0, x1, a[0][0], b0);
                addx2(x2, x3, a[0][1], b1);
                addx2(x4, x5, a[0][2], b2);
                addx2(x6, x7, a[0][3], b3);
                const unsigned o = (x0 | x1 | x2) | (x3 | x4 | x5) | (x6 | x7);
                neg[0] += (o >> 31) | (unsigned)(j >= lim0);
            }
            {
                unsigned x0, x1, x2, x3, x4, x5, x6, x7;
                addx2(x0, x1, a[1][0], b0);
                addx2(x2, x3, a[1][1], b1);
                addx2(x4, x5, a[1][2], b2);
                addx2(x6, x7, a[1][3], b3);
                const unsigned o = (x0 | x1 | x2) | (x3 | x4 | x5) | (x6 | x7);
                neg[1] += (o >> 31) | (unsigned)(j >= lim1);
            }
        }
    }

    #pragma unroll
    for (int p = 0; p < IPT; p++)
        atomicAdd(&g_counts[m * KN + ib + p * NTHR], (int)neg[p]);
}

// ---------------------------------------------------------------------------
// F) merged histogram + W1 finalize. Packed smem histogram (lo16 = matrix 0,
//    hi16 = matrix 1; max bin count 8192 < 2^16). Re-zeroes g_counts.
//    result = sum_t |cumA(t)-cumB(t)| / (N*(N-1))
// ---------------------------------------------------------------------------
__global__ __launch_bounds__(1024) void kdm_fin(float* __restrict__ out) {
    __shared__ int h[KN];        // 32 KB packed histogram
    __shared__ int wsum[32];
    const int tid = threadIdx.x, lane = tid & 31, wid = tid >> 5;

    #pragma unroll
    for (int k = tid; k < KN; k += 1024) h[k] = 0;
    __syncthreads();

    #pragma unroll
    for (int k = 0; k < 16; k++) {
        const int slot = k * 1024 + tid;
        const int i    = slot & (KN - 1);          // sorted row index
        const int neg  = g_counts[slot];
        g_counts[slot] = 0;
        const int v = ((i >> 9) + 1) * ITILE - neg;  // dominated count in [0, i]
        atomicAdd(&h[v], (slot >= KN) ? 65536 : 1);
    }
    __syncthreads();

    const int base = tid * 8;
    int d[8], tot = 0;
    #pragma unroll
    for (int k = 0; k < 8; k++) {
        const int packed = h[base + k];
        d[k] = (packed & 0xffff) - (packed >> 16);
        tot += d[k];
    }

    // inclusive warp scan of per-thread totals
    int v = tot;
    #pragma unroll
    for (int off = 1; off < 32; off <<= 1) {
        const int n = __shfl_up_sync(0xffffffffu, v, off);
        if (lane >= off) v += n;
    }
    if (lane == 31) wsum[wid] = v;
    __syncthreads();
    if (wid == 0) {
        int w = wsum[lane];
        #pragma unroll
        for (int off = 1; off < 32; off <<= 1) {
            const int n = __shfl_up_sync(0xffffffffu, w, off);
            if (lane >= off) w += n;
        }
        wsum[lane] = w;
    }
    __syncthreads();

    const int excl = v - tot + (wid ? wsum[wid - 1] : 0);
    int run = excl, acc = 0;
    #pragma unroll
    for (int k = 0; k < 8; k++) {
        run += d[k];
        acc += (run >= 0) ? run : -run;
    }

    #pragma unroll
    for (int off = 16; off; off >>= 1) acc += __shfl_down_sync(0xffffffffu, acc, off);
    __syncthreads();
    if (lane == 0) wsum[wid] = acc;
    __syncthreads();
    if (wid == 0) {
        int r = wsum[lane];
        #pragma unroll
        for (int off = 16; off; off >>= 1) r += __shfl_down_sync(0xffffffffu, r, off);
        if (lane == 0) out[0] = (float)r / ((float)KN * (float)(KN - 1));
    }
}

// ---------------------------------------------------------------------------
extern "C" void kernel_launch(void* const* d_in, const int* in_sizes, int n_in,
                              void* d_out, int out_size) {
    const float* X  = (const float*)d_in[0];
    const float* Xh = (const float*)d_in[1];
    float* out = (float*)d_out;

    kdm_sort_seg  <<<dim3(NSEG, 2),       SEGSZ>>>(X, Xh);
    kdm_rank_gather<<<dim3(KN / 256, 2),  256  >>>(X, Xh);
    kdm_dom       <<<dim3(NTILES, 2),     NTHR >>>();
    kdm_fin       <<<1, 1024>>>(out);
}

// round 5
// speedup vs baseline: 1.4131x; 1.0611x over previous
#include <cuda_runtime.h>
#include <cuda_bf16.h>
#include <cstdint>

#define KN    8192
#define KD    8
#define NTHR  256
#define IPT   2
#define ITILE 512            // i-rows per dom block
#define TJ    256            // j-rows per shared tile
#define NSEG  8
#define SEGSZ 1024
#define NTILES 272           // sum_{ti=0..15} (2*ti+2)

// Scratch (device globals; statics start zeroed, every consumer re-zeroes or
// fully overwrites -> graph replays are deterministic).
__device__ float    g_rows[2][KN][KD];   // rows sorted ascending by dim 0
__device__ unsigned g_keys[2][KN];       // segment-sorted sortable keys
__device__ int      g_kidx[2][KN];       // original row ids per segment-sorted pos
__device__ int      g_counts[2 * KN];    // per sorted-row "neg" counts

__device__ __forceinline__ unsigned f2sortable(float f) {
    unsigned u = __float_as_uint(f);
    return (u & 0x80000000u) ? ~u : (u | 0x80000000u);
}

// packed fp32x2 add (sm_100+)
__device__ __forceinline__ void addx2(unsigned &lo, unsigned &hi,
                                      unsigned long long a, unsigned long long b) {
    unsigned long long d;
    asm("add.rn.f32x2 %0, %1, %2;" : "=l"(d) : "l"(a), "l"(b));
    lo = (unsigned)d;
    hi = (unsigned)(d >> 32);
}

// ---------------------------------------------------------------------------
// S1) bitonic-sort 1024-row segments by dim-0 key
// ---------------------------------------------------------------------------
__global__ __launch_bounds__(SEGSZ) void kdm_sort_seg(const float* __restrict__ X,
                                                      const float* __restrict__ Xh) {
    const int m = blockIdx.y;
    const float* __restrict__ src = m ? Xh : X;
    __shared__ unsigned sk[SEGSZ];
    __shared__ int      si[SEGSZ];
    const int tid = threadIdx.x;
    const int e0  = blockIdx.x * SEGSZ;

    sk[tid] = f2sortable(src[(size_t)(e0 + tid) * KD]);
    si[tid] = e0 + tid;
    __syncthreads();

    for (int k = 2; k <= SEGSZ; k <<= 1) {
        for (int j = k >> 1; j > 0; j >>= 1) {
            const int ixj = tid ^ j;
            if (ixj > tid) {
                const bool up = (tid & k) == 0;
                const unsigned a = sk[tid], b = sk[ixj];
                if ((a > b) == up) {
                    sk[tid] = b; sk[ixj] = a;
                    const int t = si[tid]; si[tid] = si[ixj]; si[ixj] = t;
                }
            }
            __syncthreads();
        }
    }
    g_keys[m][e0 + tid] = sk[tid];
    g_kidx[m][e0 + tid] = si[tid];
}

// ---------------------------------------------------------------------------
// S2) global rank via cross-segment binary search, gather rows at their rank
// ---------------------------------------------------------------------------
__global__ __launch_bounds__(256) void kdm_rank_gather(const float* __restrict__ X,
                                                       const float* __restrict__ Xh) {
    const int m = blockIdx.y;
    const float* __restrict__ src = m ? Xh : X;
    __shared__ unsigned sk[KN];   // 32 KB
    for (int k = threadIdx.x; k < KN; k += 256) sk[k] = g_keys[m][k];
    __syncthreads();

    const int e   = blockIdx.x * 256 + threadIdx.x;
    const int s   = e >> 10;
    const int pos = e & (SEGSZ - 1);
    const unsigned key = sk[e];

    int rank = pos;
    #pragma unroll
    for (int t = 0; t < NSEG; t++) {
        if (t == s) continue;
        const unsigned* seg = sk + t * SEGSZ;
        int lo = 0, hi = SEGSZ;
        if (t < s) {
            while (lo < hi) { const int mid = (lo + hi) >> 1; if (seg[mid] <= key) lo = mid + 1; else hi = mid; }
        } else {
            while (lo < hi) { const int mid = (lo + hi) >> 1; if (seg[mid] <  key) lo = mid + 1; else hi = mid; }
        }
        rank += lo;
    }

    const int orig = g_kidx[m][e];
    const float4* r = reinterpret_cast<const float4*>(src + (size_t)orig * KD);
    float4* w = reinterpret_cast<float4*>(&g_rows[m][rank][0]);
    w[0] = r[0];
    w[1] = r[1];
}

// ---------------------------------------------------------------------------
// D) triangular dominance on sorted rows. d0 is implied by sort order, so the
//    sign test only covers dims 1..7 (x0 skipped). 5 blocks/SM forced.
// ---------------------------------------------------------------------------
__global__ __launch_bounds__(NTHR, 5) void kdm_dom() {
    const int m = blockIdx.y;
    const int b = blockIdx.x;
    int ti = (int)((sqrtf(4.0f * (float)b + 1.0f) - 1.0f) * 0.5f);
    while (ti * (ti + 1) > b) --ti;
    while ((ti + 1) * (ti + 2) <= b) ++ti;
    const int tj = b - ti * (ti + 1);
    const int i0 = ti << 9;
    const int j0 = tj << 8;

    __shared__ unsigned long long sj[TJ * 4];   // 8 KB, negated j-rows

    const float* gj = &g_rows[m][j0][0];
    #pragma unroll
    for (int k = threadIdx.x; k < TJ * KD / 4; k += NTHR) {
        const float4 v = reinterpret_cast<const float4*>(gj)[k];
        reinterpret_cast<float4*>(sj)[k] = make_float4(-v.x, -v.y, -v.z, -v.w);
    }

    const int ib = i0 + threadIdx.x;
    unsigned long long a[IPT][4];
    #pragma unroll
    for (int p = 0; p < IPT; p++) {
        const unsigned long long* ar =
            reinterpret_cast<const unsigned long long*>(&g_rows[m][ib + p * NTHR][0]);
        a[p][0] = ar[0]; a[p][1] = ar[1]; a[p][2] = ar[2]; a[p][3] = ar[3];
    }
    __syncthreads();

    unsigned neg[IPT] = {0, 0};

    if (j0 + TJ <= i0) {
        #pragma unroll 4
        for (int j = 0; j < TJ; j++) {
            const unsigned long long b0 = sj[j * 4 + 0];
            const unsigned long long b1 = sj[j * 4 + 1];
            const unsigned long long b2 = sj[j * 4 + 2];
            const unsigned long long b3 = sj[j * 4 + 3];
            #pragma unroll
            for (int p = 0; p < IPT; p++) {
                unsigned x0, x1, x2, x3, x4, x5, x6, x7;
                addx2(x0, x1, a[p][0], b0);   // x0 = d0 diff: implied >0, skipped
                addx2(x2, x3, a[p][1], b1);
                addx2(x4, x5, a[p][2], b2);
                addx2(x6, x7, a[p][3], b3);
                const unsigned o = (x1 | x2 | x3) | (x4 | x5 | x6) | x7;  // 3 LOP3
                neg[p] += o >> 31;
            }
        }
    } else {
        const int lim0 = ib - j0;
        const int lim1 = ib + NTHR - j0;
        #pragma unroll 4
        for (int j = 0; j < TJ; j++) {
            const unsigned long long b0 = sj[j * 4 + 0];
            const unsigned long long b1 = sj[j * 4 + 1];
            const unsigned long long b2 = sj[j * 4 + 2];
            const unsigned long long b3 = sj[j * 4 + 3];
            {
                unsigned x0, x1, x2, x3, x4, x5, x6, x7;
                addx2(x0, x1, a[0][0], b0);
                addx2(x2, x3, a[0][1], b1);
                addx2(x4, x5, a[0][2], b2);
                addx2(x6, x7, a[0][3], b3);
                const unsigned o = (x1 | x2 | x3) | (x4 | x5 | x6) | x7;
                neg[0] += (o >> 31) | (unsigned)(j >= lim0);
            }
            {
                unsigned x0, x1, x2, x3, x4, x5, x6, x7;
                addx2(x0, x1, a[1][0], b0);
                addx2(x2, x3, a[1][1], b1);
                addx2(x4, x5, a[1][2], b2);
                addx2(x6, x7, a[1][3], b3);
                const unsigned o = (x1 | x2 | x3) | (x4 | x5 | x6) | x7;
                neg[1] += (o >> 31) | (unsigned)(j >= lim1);
            }
        }
    }

    #pragma unroll
    for (int p = 0; p < IPT; p++)
        atomicAdd(&g_counts[m * KN + ib + p * NTHR], (int)neg[p]);
}

// ---------------------------------------------------------------------------
// F) merged histogram + W1 finalize, warp-aggregated atomics. Re-zeroes
//    g_counts. result = sum_t |cumA(t)-cumB(t)| / (N*(N-1))
// ---------------------------------------------------------------------------
__global__ __launch_bounds__(1024) void kdm_fin(float* __restrict__ out) {
    __shared__ int h[KN];        // 32 KB packed histogram (lo16 = A, hi16 = B)
    __shared__ int wsum[32];
    const int tid = threadIdx.x, lane = tid & 31, wid = tid >> 5;

    #pragma unroll
    for (int k = tid; k < KN; k += 1024) h[k] = 0;
    __syncthreads();

    #pragma unroll
    for (int k = 0; k < 16; k++) {
        const int slot = k * 1024 + tid;
        const int i    = slot & (KN - 1);
        const int neg  = g_counts[slot];
        g_counts[slot] = 0;
        const int v = ((i >> 9) + 1) * ITILE - neg;       // dominated count
        // warp-aggregate same-v adds (matrix is uniform per k across the warp)
        const unsigned mask = __match_any_sync(0xffffffffu, v);
        if ((int)(__ffs(mask) - 1) == lane) {
            const int add = (slot >= KN) ? 65536 : 1;
            atomicAdd(&h[v], add * __popc(mask));
        }
    }
    __syncthreads();

    const int base = tid * 8;
    int d[8], tot = 0;
    #pragma unroll
    for (int k = 0; k < 8; k++) {
        const int packed = h[base + k];
        d[k] = (packed & 0xffff) - (packed >> 16);
        tot += d[k];
    }

    int v = tot;
    #pragma unroll
    for (int off = 1; off < 32; off <<= 1) {
        const int n = __shfl_up_sync(0xffffffffu, v, off);
        if (lane >= off) v += n;
    }
    if (lane == 31) wsum[wid] = v;
    __syncthreads();
    if (wid == 0) {
        int w = wsum[lane];
        #pragma unroll
        for (int off = 1; off < 32; off <<= 1) {
            const int n = __shfl_up_sync(0xffffffffu, w, off);
            if (lane >= off) w += n;
        }
        wsum[lane] = w;
    }
    __syncthreads();

    const int excl = v - tot + (wid ? wsum[wid - 1] : 0);
    int run = excl, acc = 0;
    #pragma unroll
    for (int k = 0; k < 8; k++) {
        run += d[k];
        acc += (run >= 0) ? run : -run;
    }

    #pragma unroll
    for (int off = 16; off; off >>= 1) acc += __shfl_down_sync(0xffffffffu, acc, off);
    __syncthreads();
    if (lane == 0) wsum[wid] = acc;
    __syncthreads();
    if (wid == 0) {
        int r = wsum[lane];
        #pragma unroll
        for (int off = 16; off; off >>= 1) r += __shfl_down_sync(0xffffffffu, r, off);
        if (lane == 0) out[0] = (float)r / ((float)KN * (float)(KN - 1));
    }
}

// ---------------------------------------------------------------------------
extern "C" void kernel_launch(void* const* d_in, const int* in_sizes, int n_in,
                              void* d_out, int out_size) {
    const float* X  = (const float*)d_in[0];
    const float* Xh = (const float*)d_in[1];
    float* out = (float*)d_out;

    kdm_sort_seg   <<<dim3(NSEG, 2),      SEGSZ>>>(X, Xh);
    kdm_rank_gather<<<dim3(KN / 256, 2),  256  >>>(X, Xh);
    kdm_dom        <<<dim3(NTILES, 2),    NTHR >>>();
    kdm_fin        <<<1, 1024>>>(out);
}

// round 6
// speedup vs baseline: 1.7536x; 1.2410x over previous
#include <cuda_runtime.h>
#include <cuda_bf16.h>
#include <cstdint>

#define KN    8192
#define KD    8
#define NTHR  256
#define IPT   4
#define ITILE 1024           // i-rows per dom block (IPT * NTHR)
#define TJ    256            // j-rows per shared tile
#define NSEG  8
#define SEGSZ 1024
#define NTILES 144           // sum_{ti=0..7} (4*ti+4)

// Device-global scratch. Statics start zeroed; every consumer re-zeroes or
// fully overwrites what it reads -> graph replays are deterministic.
__device__ unsigned       g_keys[16][KN];        // [m*8+d] segment-sorted keys
__device__ int            g_kidx[16][KN];        // original row id per seg-sorted pos
__device__ unsigned short g_rank16[2][KN][KD];   // per-row per-dim rank
__device__ uint4          g_prow[2][KN];         // packed fp16 rank rows, sorted by d0 rank
__device__ int            g_counts[2 * KN];      // per sorted-row "neg" counts
__device__ int            g_hd[KN];              // signed diff histogram (A minus B)

__device__ __forceinline__ unsigned f2sortable(float f) {
    unsigned u = __float_as_uint(f);
    return (u & 0x80000000u) ? ~u : (u | 0x80000000u);
}

// packed fp16x2 add (sign-exact; FTZ-safe for sign tests)
__device__ __forceinline__ unsigned hadd2(unsigned a, unsigned b) {
    unsigned d;
    asm("add.rn.f16x2 %0, %1, %2;" : "=r"(d) : "r"(a), "r"(b));
    return d;
}

// ---------------------------------------------------------------------------
// S1) bitonic-sort 1024-element segments of column d of matrix m.
//     grid = (NSEG, 16) where y = m*8 + d.
// ---------------------------------------------------------------------------
__global__ __launch_bounds__(SEGSZ) void kdm_sort_seg(const float* __restrict__ X,
                                                      const float* __restrict__ Xh) {
    const int md = blockIdx.y;
    const int d  = md & 7;
    const float* __restrict__ src = (md >> 3) ? Xh : X;
    __shared__ unsigned sk[SEGSZ];
    __shared__ int      si[SEGSZ];
    const int tid = threadIdx.x;
    const int e0  = blockIdx.x * SEGSZ;

    sk[tid] = f2sortable(src[(size_t)(e0 + tid) * KD + d]);
    si[tid] = e0 + tid;
    __syncthreads();

    for (int k = 2; k <= SEGSZ; k <<= 1) {
        for (int j = k >> 1; j > 0; j >>= 1) {
            const int ixj = tid ^ j;
            if (ixj > tid) {
                const bool up = (tid & k) == 0;
                const unsigned a = sk[tid], b = sk[ixj];
                if ((a > b) == up) {
                    sk[tid] = b; sk[ixj] = a;
                    const int t = si[tid]; si[tid] = si[ixj]; si[ixj] = t;
                }
            }
            __syncthreads();
        }
    }
    g_keys[md][e0 + tid] = sk[tid];
    g_kidx[md][e0 + tid] = si[tid];
}

// ---------------------------------------------------------------------------
// S2) global rank per column via cross-segment binary search; scatter the
//     16-bit rank to the element's original row. grid = (KN/256, 16).
// ---------------------------------------------------------------------------
__global__ __launch_bounds__(256) void kdm_rank() {
    const int md = blockIdx.y;
    __shared__ unsigned sk[KN];   // 32 KB
    for (int k = threadIdx.x; k < KN; k += 256) sk[k] = g_keys[md][k];
    __syncthreads();

    const int e   = blockIdx.x * 256 + threadIdx.x;
    const int s   = e >> 10;
    const int pos = e & (SEGSZ - 1);
    const unsigned key = sk[e];

    int rank = pos;
    #pragma unroll
    for (int t = 0; t < NSEG; t++) {
        if (t == s) continue;
        const unsigned* seg = sk + t * SEGSZ;
        int lo = 0, hi = SEGSZ;
        if (t < s) {  // count <= key
            while (lo < hi) { const int mid = (lo + hi) >> 1; if (seg[mid] <= key) lo = mid + 1; else hi = mid; }
        } else {      // count < key
            while (lo < hi) { const int mid = (lo + hi) >> 1; if (seg[mid] <  key) lo = mid + 1; else hi = mid; }
        }
        rank += lo;
    }
    g_rank16[md >> 3][g_kidx[md][e]][md & 7] = (unsigned short)rank;
}

// ---------------------------------------------------------------------------
// S3) pack each row's dims 1..7 ranks (+0x400 fp16 bias) into a uint4 and
//     place it at its d0-rank position. grid = (KN/256, 2).
// ---------------------------------------------------------------------------
__global__ __launch_bounds__(256) void kdm_pack() {
    const int m   = blockIdx.y;
    const int row = blockIdx.x * 256 + threadIdx.x;
    const uint4 q = *reinterpret_cast<const uint4*>(&g_rank16[m][row][0]);
    const unsigned OFF = 0x04000400u;
    const unsigned d0 = q.x & 0xffffu;      // d0 rank = sorted position
    uint4 o;
    o.x = ((q.x >> 16) | (q.y << 16)) + OFF;   // d1, d2
    o.y = ((q.y >> 16) | (q.z << 16)) + OFF;   // d3, d4
    o.z = ((q.z >> 16) | (q.w << 16)) + OFF;   // d5, d6
    o.w = ( q.w >> 16)                + OFF;   // d7, pad(0x0400)
    g_prow[m][d0] = o;
}

// ---------------------------------------------------------------------------
// D) triangular dominance on rank-sorted packed rows. Thread owns 4 i-rows.
//    "neg" counts (not-dominated OR masked-j); H recovers dominated counts.
// ---------------------------------------------------------------------------
__global__ __launch_bounds__(NTHR, 6) void kdm_dom() {
    const int m = blockIdx.y;
    const int b = blockIdx.x;
    // tile start(ti) = 2*ti*(ti+1); strip ti has 4*ti+4 j-tiles
    int ti = (int)((sqrtf(2.0f * (float)b + 1.0f) - 1.0f) * 0.5f);
    while (2 * ti * (ti + 1) > b) --ti;
    while (2 * (ti + 1) * (ti + 2) <= b) ++ti;
    const int tj = b - 2 * ti * (ti + 1);
    const int i0 = ti << 10;
    const int j0 = tj << 8;

    __shared__ uint4 sj[TJ];    // 4 KB, fp16-negated j-rows

    for (int k = threadIdx.x; k < TJ; k += NTHR) {
        uint4 v = g_prow[m][j0 + k];
        v.x ^= 0x80008000u; v.y ^= 0x80008000u;
        v.z ^= 0x80008000u; v.w ^= 0x80008000u;
        sj[k] = v;
    }

    const int ib = i0 + threadIdx.x;
    uint4 a[IPT];
    #pragma unroll
    for (int p = 0; p < IPT; p++) a[p] = g_prow[m][ib + p * NTHR];
    __syncthreads();

    unsigned neg[IPT] = {0, 0, 0, 0};

    if (j0 + TJ <= i0) {
        #pragma unroll 4
        for (int j = 0; j < TJ; j++) {
            const uint4 bv = sj[j];
            #pragma unroll
            for (int p = 0; p < IPT; p++) {
                const unsigned x0 = hadd2(a[p].x, bv.x);
                const unsigned x1 = hadd2(a[p].y, bv.y);
                const unsigned x2 = hadd2(a[p].z, bv.z);
                const unsigned x3 = hadd2(a[p].w, bv.w);
                const unsigned o  = x0 | x1 | x2;                 // 1 LOP3
                const unsigned s  = (o | x3) & 0x80008000u;       // 1 LOP3
                neg[p] += min(s, 1u);                             // IMNMX + IADD
            }
        }
    } else {
        int lim[IPT];
        #pragma unroll
        for (int p = 0; p < IPT; p++) lim[p] = ib + p * NTHR - j0;
        #pragma unroll 4
        for (int j = 0; j < TJ; j++) {
            const uint4 bv = sj[j];
            #pragma unroll
            for (int p = 0; p < IPT; p++) {
                const unsigned x0 = hadd2(a[p].x, bv.x);
                const unsigned x1 = hadd2(a[p].y, bv.y);
                const unsigned x2 = hadd2(a[p].z, bv.z);
                const unsigned x3 = hadd2(a[p].w, bv.w);
                const unsigned o  = x0 | x1 | x2;
                const unsigned s  = (o | x3) & 0x80008000u;
                neg[p] += min(s, 1u) | (unsigned)(j >= lim[p]);
            }
        }
    }

    #pragma unroll
    for (int p = 0; p < IPT; p++)
        atomicAdd(&g_counts[m * KN + ib + p * NTHR], (int)neg[p]);
}

// ---------------------------------------------------------------------------
// H) signed diff histogram across 16 blocks (warp-aggregated global atomics).
//    dominated(i) = 1024*(ti+1) - neg(i). Re-zeroes g_counts.
// ---------------------------------------------------------------------------
__global__ __launch_bounds__(1024) void kdm_hist() {
    const int slot = blockIdx.x * 1024 + threadIdx.x;
    const int lane = threadIdx.x & 31;
    const int neg  = g_counts[slot];
    g_counts[slot] = 0;
    const int i = slot & (KN - 1);
    const int v = (((i >> 10) + 1) << 10) - neg;
    const int delta = (slot >= KN) ? -1 : 1;     // uniform across each warp
    const unsigned mask = __match_any_sync(0xffffffffu, v);
    if ((int)(__ffs(mask) - 1) == lane)
        atomicAdd(&g_hd[v], delta * __popc(mask));
}

// ---------------------------------------------------------------------------
// F) W1 finalize: sum_t |cum diff(t)| / (N*(N-1)). Re-zeroes g_hd.
// ---------------------------------------------------------------------------
__global__ __launch_bounds__(1024) void kdm_fin(float* __restrict__ out) {
    __shared__ int wsum[32];
    const int tid = threadIdx.x, lane = tid & 31, wid = tid >> 5;
    const int base = tid * 8;

    int d[8], tot = 0;
    #pragma unroll
    for (int k = 0; k < 8; k++) {
        d[k] = g_hd[base + k];
        g_hd[base + k] = 0;
        tot += d[k];
    }

    int v = tot;
    #pragma unroll
    for (int off = 1; off < 32; off <<= 1) {
        const int n = __shfl_up_sync(0xffffffffu, v, off);
        if (lane >= off) v += n;
    }
    if (lane == 31) wsum[wid] = v;
    __syncthreads();
    if (wid == 0) {
        int w = wsum[lane];
        #pragma unroll
        for (int off = 1; off < 32; off <<= 1) {
            const int n = __shfl_up_sync(0xffffffffu, w, off);
            if (lane >= off) w += n;
        }
        wsum[lane] = w;
    }
    __syncthreads();

    const int excl = v - tot + (wid ? wsum[wid - 1] : 0);
    int run = excl, acc = 0;
    #pragma unroll
    for (int k = 0; k < 8; k++) {
        run += d[k];
        acc += (run >= 0) ? run : -run;
    }

    #pragma unroll
    for (int off = 16; off; off >>= 1) acc += __shfl_down_sync(0xffffffffu, acc, off);
    __syncthreads();
    if (lane == 0) wsum[wid] = acc;
    __syncthreads();
    if (wid == 0) {
        int r = wsum[lane];
        #pragma unroll
        for (int off = 16; off; off >>= 1) r += __shfl_down_sync(0xffffffffu, r, off);
        if (lane == 0) out[0] = (float)r / ((float)KN * (float)(KN - 1));
    }
}

// ---------------------------------------------------------------------------
extern "C" void kernel_launch(void* const* d_in, const int* in_sizes, int n_in,
                              void* d_out, int out_size) {
    const float* X  = (const float*)d_in[0];
    const float* Xh = (const float*)d_in[1];
    float* out = (float*)d_out;

    kdm_sort_seg<<<dim3(NSEG, 16),     SEGSZ>>>(X, Xh);
    kdm_rank    <<<dim3(KN / 256, 16), 256  >>>();
    kdm_pack    <<<dim3(KN / 256, 2),  256  >>>();
    kdm_dom     <<<dim3(NTILES, 2),    NTHR >>>();
    kdm_hist    <<<2 * KN / 1024,      1024 >>>();
    kdm_fin     <<<1, 1024>>>(out);
}

// round 7
// speedup vs baseline: 1.9544x; 1.1145x over previous
#include <cuda_runtime.h>
#include <cuda_bf16.h>
#include <cstdint>

#define KN    8192
#define KD    8
#define NTHR  256
#define IPT   4
#define ITILE 1024           // i-rows per dom block (IPT * NTHR)
#define TJ    128            // j-rows per shared tile
#define NSEG  8
#define SEGSZ 1024
#define NTILES 288           // sum_{ti=0..7} 8*(ti+1)

// Device-global scratch. Statics start zeroed; every consumer re-zeroes or
// fully overwrites what it reads -> graph replays are deterministic.
__device__ unsigned       g_keys[16][KN];        // [m*8+d] segment-sorted keys
__device__ int            g_kidx[16][KN];        // original row id per seg-sorted pos
__device__ unsigned short g_rank16[2][KN][KD];   // per-row per-dim rank
__device__ uint4          g_prow[2][KN];         // packed fp16 rank rows, sorted by d0 rank
__device__ int            g_counts[2 * KN];      // per sorted-row "neg" counts
__device__ int            g_hd[KN];              // signed diff histogram (A minus B)

__device__ __forceinline__ unsigned f2sortable(float f) {
    unsigned u = __float_as_uint(f);
    return (u & 0x80000000u) ? ~u : (u | 0x80000000u);
}

// packed fp16x2 add (sign-exact for rank differences)
__device__ __forceinline__ unsigned hadd2(unsigned a, unsigned b) {
    unsigned d;
    asm("add.rn.f16x2 %0, %1, %2;" : "=r"(d) : "r"(a), "r"(b));
    return d;
}

// ---------------------------------------------------------------------------
// S1) bitonic-sort 1024-element segments of column d of matrix m.
//     64-bit (key<<32 | idx) elements; distances j<=16 run as register
//     shfl passes (no barriers). grid = (NSEG, 16), y = m*8 + d.
// ---------------------------------------------------------------------------
__global__ __launch_bounds__(SEGSZ) void kdm_sort_seg(const float* __restrict__ X,
                                                      const float* __restrict__ Xh) {
    const int md = blockIdx.y;
    const int d  = md & 7;
    const float* __restrict__ src = (md >> 3) ? Xh : X;
    __shared__ unsigned long long s[SEGSZ];   // 8 KB
    const int tid = threadIdx.x;
    const int e0  = blockIdx.x * SEGSZ;

    s[tid] = ((unsigned long long)f2sortable(src[(size_t)(e0 + tid) * KD + d]) << 32)
             | (unsigned)(e0 + tid);
    __syncthreads();

    for (int k = 2; k <= SEGSZ; k <<= 1) {
        const bool up = (tid & k) == 0;
        // smem passes: distance >= 32
        for (int j = k >> 1; j >= 32; j >>= 1) {
            const int ixj = tid ^ j;
            if (ixj > tid) {
                const unsigned long long a = s[tid], b = s[ixj];
                if ((a > b) == up) { s[tid] = b; s[ixj] = a; }
            }
            __syncthreads();
        }
        // register shfl passes: distance <= 16
        unsigned long long v = s[tid];
        #pragma unroll
        for (int j = 16; j >= 1; j >>= 1) {
            if (j <= (k >> 1)) {
                const unsigned long long o = __shfl_xor_sync(0xffffffffu, v, j);
                const bool keepmin = (((tid & j) == 0) == up);
                const bool omin = (o < v);
                v = (keepmin == omin) ? o : v;
            }
        }
        s[tid] = v;
        __syncthreads();
    }
    const unsigned long long r = s[tid];
    g_keys[md][e0 + tid] = (unsigned)(r >> 32);
    g_kidx[md][e0 + tid] = (int)(unsigned)r;
}

// ---------------------------------------------------------------------------
// S2) global rank per column via cross-segment binary search; scatter the
//     16-bit rank to the element's original row. grid = (KN/256, 16).
// ---------------------------------------------------------------------------
__global__ __launch_bounds__(256) void kdm_rank() {
    const int md = blockIdx.y;
    __shared__ unsigned sk[KN];   // 32 KB
    for (int k = threadIdx.x; k < KN; k += 256) sk[k] = g_keys[md][k];
    __syncthreads();

    const int e   = blockIdx.x * 256 + threadIdx.x;
    const int s   = e >> 10;
    const int pos = e & (SEGSZ - 1);
    const unsigned key = sk[e];

    int rank = pos;
    #pragma unroll
    for (int t = 0; t < NSEG; t++) {
        if (t == s) continue;
        const unsigned* seg = sk + t * SEGSZ;
        int lo = 0, hi = SEGSZ;
        if (t < s) {  // count <= key
            while (lo < hi) { const int mid = (lo + hi) >> 1; if (seg[mid] <= key) lo = mid + 1; else hi = mid; }
        } else {      // count < key
            while (lo < hi) { const int mid = (lo + hi) >> 1; if (seg[mid] <  key) lo = mid + 1; else hi = mid; }
        }
        rank += lo;
    }
    g_rank16[md >> 3][g_kidx[md][e]][md & 7] = (unsigned short)rank;
}

// ---------------------------------------------------------------------------
// S3) pack dims 1..7 ranks (+0x400 fp16 bias) into a uint4 at the row's
//     d0-rank position. grid = (KN/256, 2).
// ---------------------------------------------------------------------------
__global__ __launch_bounds__(256) void kdm_pack() {
    const int m   = blockIdx.y;
    const int row = blockIdx.x * 256 + threadIdx.x;
    const uint4 q = *reinterpret_cast<const uint4*>(&g_rank16[m][row][0]);
    const unsigned OFF = 0x04000400u;
    const unsigned d0 = q.x & 0xffffu;
    uint4 o;
    o.x = ((q.x >> 16) | (q.y << 16)) + OFF;   // d1, d2
    o.y = ((q.y >> 16) | (q.z << 16)) + OFF;   // d3, d4
    o.z = ((q.z >> 16) | (q.w << 16)) + OFF;   // d5, d6
    o.w = ( q.w >> 16)                + OFF;   // d7, pad
    g_prow[m][d0] = o;
}

// ---------------------------------------------------------------------------
// D) triangular dominance on rank-sorted packed rows. Thread owns 4 i-rows.
//    Strip ti (1024 i's) has 8*(ti+1) j-tiles of 128; start = 4*ti*(ti+1).
// ---------------------------------------------------------------------------
__global__ __launch_bounds__(NTHR, 6) void kdm_dom() {
    const int m = blockIdx.y;
    const int b = blockIdx.x;
    int ti = (int)((sqrtf((float)b + 1.0f) - 1.0f) * 0.5f);
    while (4 * ti * (ti + 1) > b) --ti;
    while (4 * (ti + 1) * (ti + 2) <= b) ++ti;
    const int tj = b - 4 * ti * (ti + 1);
    const int i0 = ti << 10;
    const int j0 = tj << 7;

    __shared__ uint4 sj[TJ];    // 2 KB, fp16-negated j-rows

    if (threadIdx.x < TJ) {
        uint4 v = g_prow[m][j0 + threadIdx.x];
        v.x ^= 0x80008000u; v.y ^= 0x80008000u;
        v.z ^= 0x80008000u; v.w ^= 0x80008000u;
        sj[threadIdx.x] = v;
    }

    const int ib = i0 + threadIdx.x;
    uint4 a[IPT];
    #pragma unroll
    for (int p = 0; p < IPT; p++) a[p] = g_prow[m][ib + p * NTHR];
    __syncthreads();

    unsigned neg[IPT] = {0, 0, 0, 0};

    if (j0 + TJ <= i0) {
        #pragma unroll 4
        for (int j = 0; j < TJ; j++) {
            const uint4 bv = sj[j];
            #pragma unroll
            for (int p = 0; p < IPT; p++) {
                const unsigned x0 = hadd2(a[p].x, bv.x);
                const unsigned x1 = hadd2(a[p].y, bv.y);
                const unsigned x2 = hadd2(a[p].z, bv.z);
                const unsigned x3 = hadd2(a[p].w, bv.w);
                const unsigned o  = x0 | x1 | x2;
                const unsigned sb = (o | x3) & 0x80008000u;
                neg[p] += min(sb, 1u);
            }
        }
    } else {
        int lim[IPT];
        #pragma unroll
        for (int p = 0; p < IPT; p++) lim[p] = ib + p * NTHR - j0;
        #pragma unroll 4
        for (int j = 0; j < TJ; j++) {
            const uint4 bv = sj[j];
            #pragma unroll
            for (int p = 0; p < IPT; p++) {
                const unsigned x0 = hadd2(a[p].x, bv.x);
                const unsigned x1 = hadd2(a[p].y, bv.y);
                const unsigned x2 = hadd2(a[p].z, bv.z);
                const unsigned x3 = hadd2(a[p].w, bv.w);
                const unsigned o  = x0 | x1 | x2;
                const unsigned sb = (o | x3) & 0x80008000u;
                neg[p] += min(sb, 1u) | (unsigned)(j >= lim[p]);
            }
        }
    }

    #pragma unroll
    for (int p = 0; p < IPT; p++)
        atomicAdd(&g_counts[m * KN + ib + p * NTHR], (int)neg[p]);
}

// ---------------------------------------------------------------------------
// H) signed diff histogram, 16 blocks, warp-aggregated global atomics.
//    dominated(i) = 1024*(ti+1) - neg(i). Re-zeroes g_counts.
// ---------------------------------------------------------------------------
__global__ __launch_bounds__(1024) void kdm_hist() {
    const int slot = blockIdx.x * 1024 + threadIdx.x;
    const int lane = threadIdx.x & 31;
    const int neg  = g_counts[slot];
    g_counts[slot] = 0;
    const int i = slot & (KN - 1);
    const int v = (((i >> 10) + 1) << 10) - neg;
    const int delta = (slot >= KN) ? -1 : 1;
    const unsigned mask = __match_any_sync(0xffffffffu, v);
    if ((int)(__ffs(mask) - 1) == lane)
        atomicAdd(&g_hd[v], delta * __popc(mask));
}

// ---------------------------------------------------------------------------
// F) W1 finalize: sum_t |cum diff(t)| / (N*(N-1)). Re-zeroes g_hd.
// ---------------------------------------------------------------------------
__global__ __launch_bounds__(1024) void kdm_fin(float* __restrict__ out) {
    __shared__ int wsum[32];
    const int tid = threadIdx.x, lane = tid & 31, wid = tid >> 5;
    const int base = tid * 8;

    int d[8], tot = 0;
    #pragma unroll
    for (int k = 0; k < 8; k++) {
        d[k] = g_hd[base + k];
        g_hd[base + k] = 0;
        tot += d[k];
    }

    int v = tot;
    #pragma unroll
    for (int off = 1; off < 32; off <<= 1) {
        const int n = __shfl_up_sync(0xffffffffu, v, off);
        if (lane >= off) v += n;
    }
    if (lane == 31) wsum[wid] = v;
    __syncthreads();
    if (wid == 0) {
        int w = wsum[lane];
        #pragma unroll
        for (int off = 1; off < 32; off <<= 1) {
            const int n = __shfl_up_sync(0xffffffffu, w, off);
            if (lane >= off) w += n;
        }
        wsum[lane] = w;
    }
    __syncthreads();

    const int excl = v - tot + (wid ? wsum[wid - 1] : 0);
    int run = excl, acc = 0;
    #pragma unroll
    for (int k = 0; k < 8; k++) {
        run += d[k];
        acc += (run >= 0) ? run : -run;
    }

    #pragma unroll
    for (int off = 16; off; off >>= 1) acc += __shfl_down_sync(0xffffffffu, acc, off);
    __syncthreads();
    if (lane == 0) wsum[wid] = acc;
    __syncthreads();
    if (wid == 0) {
        int r = wsum[lane];
        #pragma unroll
        for (int off = 16; off; off >>= 1) r += __shfl_down_sync(0xffffffffu, r, off);
        if (lane == 0) out[0] = (float)r / ((float)KN * (float)(KN - 1));
    }
}

// ---------------------------------------------------------------------------
extern "C" void kernel_launch(void* const* d_in, const int* in_sizes, int n_in,
                              void* d_out, int out_size) {
    const float* X  = (const float*)d_in[0];
    const float* Xh = (const float*)d_in[1];
    float* out = (float*)d_out;

    kdm_sort_seg<<<dim3(NSEG, 16),     SEGSZ>>>(X, Xh);
    kdm_rank    <<<dim3(KN / 256, 16), 256  >>>();
    kdm_pack    <<<dim3(KN / 256, 2),  256  >>>();
    kdm_dom     <<<dim3(NTILES, 2),    NTHR >>>();
    kdm_hist    <<<2 * KN / 1024,      1024 >>>();
    kdm_fin     <<<1, 1024>>>(out);
}